// round 8
// baseline (speedup 1.0000x reference)
#include <cuda_runtime.h>
#include <cuda_bf16.h>
#include <cstdint>
#include <cstddef>

#define BB 4
#define NO3 384
#define FFQ 64
#define TTT 512
#define NHH 8
#define HDD 1024
#define CF 8192
#define EPSV 1e-5f

// ---------------- scratch ----------------
__device__ float g_xt [BB*TTT*CF];
__device__ float g_v  [BB*NHH*TTT*HDD];
__device__ float g_s  [BB*NHH*TTT*TTT];
__device__ float g_c  [BB*128*TTT*FFQ];
__device__ float g_y  [BB*TTT*CF];
__device__ __nv_bfloat16 g_wqhb[NO3*128], g_wqlb[NO3*128];
__device__ __nv_bfloat16 g_wphb[128*128], g_wplb[128*128];
__device__ __nv_bfloat16 g_qh[BB*NHH*TTT*HDD];
__device__ __nv_bfloat16 g_ql[BB*NHH*TTT*HDD];
__device__ __nv_bfloat16 g_kh[BB*NHH*TTT*HDD];
__device__ __nv_bfloat16 g_kl[BB*NHH*TTT*HDD];
__device__ __nv_bfloat16 g_vth[BB*NHH*HDD*TTT];
__device__ __nv_bfloat16 g_vtl[BB*NHH*HDD*TTT];
__device__ __nv_bfloat16 g_ph[BB*NHH*TTT*TTT];
__device__ __nv_bfloat16 g_pl[BB*NHH*TTT*TTT];

// ---------------- helpers ----------------
__device__ __forceinline__ uint32_t smem_u32(const void* p) {
    uint32_t a;
    asm("{ .reg .u64 t; cvta.to.shared.u64 t, %1; cvt.u32.u64 %0, t; }" : "=r"(a) : "l"(p));
    return a;
}
__device__ __forceinline__ void ldsm4(uint32_t* r, uint32_t a) {
    asm volatile("ldmatrix.sync.aligned.m8n8.x4.shared.b16 {%0,%1,%2,%3}, [%4];"
        : "=r"(r[0]), "=r"(r[1]), "=r"(r[2]), "=r"(r[3]) : "r"(a));
}
__device__ __forceinline__ void mmabf(float* c, const uint32_t* a, const uint32_t* b) {
    asm volatile("mma.sync.aligned.m16n8k16.row.col.f32.bf16.bf16.f32 "
        "{%0,%1,%2,%3}, {%4,%5,%6,%7}, {%8,%9}, {%0,%1,%2,%3};"
        : "+f"(c[0]), "+f"(c[1]), "+f"(c[2]), "+f"(c[3])
        : "r"(a[0]), "r"(a[1]), "r"(a[2]), "r"(a[3]), "r"(b[0]), "r"(b[1]));
}
__device__ __forceinline__ void split_bf(float f, __nv_bfloat16& h, __nv_bfloat16& l) {
    h = __float2bfloat16(f);
    l = __float2bfloat16(f - __bfloat162float(h));
}
__device__ __forceinline__ void cpa16(uint32_t s, const void* g) {
    asm volatile("cp.async.cg.shared.global [%0], [%1], 16;" :: "r"(s), "l"(g));
}
#define CPA_COMMIT() asm volatile("cp.async.commit_group;" ::: "memory")
template<int N> __device__ __forceinline__ void cpa_wait() {
    asm volatile("cp.async.wait_group %0;" :: "n"(N) : "memory");
}

// attention tiles: 128x64 bf16, stride 72 elems
#define SROW 72
#define TILEB 18432
#define SMEMSZ_AT (2*4*TILEB)   // 147456: 2 stages x 4 tiles
// conv tiles: stride 136 elems
#define SROWK 136

// ======== attention GEMM core: C[128,128] += (Ah+Al)(Bh+Bl)^T, cp.async double-buffered ========
// MODE 0: masked+scaled direct store (k2a). MODE 1: transposed store into g_c (k2c, fuses old k3).
template<int MODE>
__device__ __forceinline__ void mma_core(
    const __nv_bfloat16* __restrict__ Ah, const __nv_bfloat16* __restrict__ Al, int lda,
    const __nv_bfloat16* __restrict__ Bh, const __nv_bfloat16* __restrict__ Bl, int ldb,
    int kmax, float* __restrict__ outp, int ldo, int row0, int col0, float scale,
    int bh, int dt, int qt)
{
    extern __shared__ __align__(16) uint8_t smraw[];
    uint32_t su = smem_u32(smraw);
    int tid = threadIdx.x, lane = tid & 31, wid = tid >> 5;
    int wm = wid >> 2, wn = wid & 3;

    float acc[4][4][4];
    #pragma unroll
    for (int i = 0; i < 4; ++i)
        #pragma unroll
        for (int j = 0; j < 4; ++j)
            #pragma unroll
            for (int q = 0; q < 4; ++q) acc[i][j][q] = 0.f;

    uint32_t aoff = (uint32_t)(((wm*64 + (lane & 15))*SROW + (lane >> 4)*8) * 2);
    uint32_t boff = (uint32_t)(((wn*32 + ((lane & 7) + ((lane >> 4) << 3)))*SROW + ((lane >> 3) & 1)*8) * 2);

    int row = tid >> 1, half = tid & 1;
    auto stage = [&](int buf, int k0) {
        const __nv_bfloat16* s0 = Ah + (size_t)row*lda + k0 + half*32;
        const __nv_bfloat16* s1 = Al + (size_t)row*lda + k0 + half*32;
        const __nv_bfloat16* s2 = Bh + (size_t)row*ldb + k0 + half*32;
        const __nv_bfloat16* s3 = Bl + (size_t)row*ldb + k0 + half*32;
        uint32_t d = su + buf*(4*TILEB) + (uint32_t)((row*SROW + half*32)*2);
        #pragma unroll
        for (int j = 0; j < 4; ++j) {
            cpa16(d + j*16,           s0 + j*8);
            cpa16(d + TILEB + j*16,   s1 + j*8);
            cpa16(d + 2*TILEB + j*16, s2 + j*8);
            cpa16(d + 3*TILEB + j*16, s3 + j*8);
        }
    };

    stage(0, 0); CPA_COMMIT();
    int C = kmax >> 6;
    for (int c = 0; c < C; ++c) {
        if (c + 1 < C) { stage((c+1)&1, (c+1)*64); CPA_COMMIT(); cpa_wait<1>(); }
        else           { cpa_wait<0>(); }
        __syncthreads();
        uint32_t base = su + (c&1)*(4*TILEB);
        uint32_t uAh = base, uAl = base + TILEB, uBh = base + 2*TILEB, uBl = base + 3*TILEB;
        #pragma unroll
        for (int kk = 0; kk < 4; ++kk) {
            uint32_t bh_[4][2], bl_[4][2];
            #pragma unroll
            for (int ng = 0; ng < 2; ++ng) {
                uint32_t r4[4];
                ldsm4(r4, uBh + boff + ng*(16*SROW*2) + kk*32);
                bh_[ng*2][0] = r4[0]; bh_[ng*2][1] = r4[1];
                bh_[ng*2+1][0] = r4[2]; bh_[ng*2+1][1] = r4[3];
                ldsm4(r4, uBl + boff + ng*(16*SROW*2) + kk*32);
                bl_[ng*2][0] = r4[0]; bl_[ng*2][1] = r4[1];
                bl_[ng*2+1][0] = r4[2]; bl_[ng*2+1][1] = r4[3];
            }
            #pragma unroll
            for (int mf = 0; mf < 4; ++mf) {
                uint32_t ah[4], al[4];
                ldsm4(ah, uAh + aoff + mf*(16*SROW*2) + kk*32);
                ldsm4(al, uAl + aoff + mf*(16*SROW*2) + kk*32);
                #pragma unroll
                for (int nf = 0; nf < 4; ++nf) {
                    mmabf(acc[mf][nf], ah, bh_[nf]);
                    mmabf(acc[mf][nf], ah, bl_[nf]);
                    mmabf(acc[mf][nf], al, bh_[nf]);
                }
            }
        }
        __syncthreads();
    }

    int rloc0 = wm*64 + (lane >> 2);
    int cloc  = wn*32 + (lane & 3)*2;
    if (MODE == 0) {
        #pragma unroll
        for (int mf = 0; mf < 4; ++mf) {
            #pragma unroll
            for (int nf = 0; nf < 4; ++nf) {
                int cc = cloc + nf*8;
                int cg = col0 + cc;
                #pragma unroll
                for (int h = 0; h < 2; ++h) {
                    int rl = rloc0 + mf*16 + h*8;
                    int rg = row0 + rl;
                    float v0 = acc[mf][nf][2*h], v1 = acc[mf][nf][2*h+1];
                    v0 = (cg     <= rg) ? v0*scale : -1e30f;
                    v1 = (cg + 1 <= rg) ? v1*scale : -1e30f;
                    *(float2*)(outp + (size_t)rl*ldo + cc) = make_float2(v0, v1);
                }
            }
        }
    } else {
        // park in smem [t][d] (stride 132), then write transposed [d][t] coalesced into g_c
        float* Y = (float*)smraw;
        #pragma unroll
        for (int mf = 0; mf < 4; ++mf)
            #pragma unroll
            for (int nf = 0; nf < 4; ++nf) {
                int cc = cloc + nf*8;
                #pragma unroll
                for (int h = 0; h < 2; ++h) {
                    int rl = rloc0 + mf*16 + h*8;
                    *(float2*)(Y + rl*132 + cc) = make_float2(acc[mf][nf][2*h], acc[mf][nf][2*h+1]);
                }
            }
        __syncthreads();
        size_t cb = (size_t)(bh*16 + dt*2)*32768 + qt*128;
        int tq = tid & 3;
        #pragma unroll
        for (int pass = 0; pass < 2; ++pass) {
            int dcol = (tid >> 2) + pass*64;
            float* dst = g_c + cb + (size_t)(dcol >> 6)*32768 + (dcol & 63)*512;
            #pragma unroll
            for (int j = 0; j < 8; ++j) {
                int t0 = tq*4 + j*16;
                float4 v;
                v.x = Y[(t0+0)*132 + dcol];
                v.y = Y[(t0+1)*132 + dcol];
                v.z = Y[(t0+2)*132 + dcol];
                v.w = Y[(t0+3)*132 + dcol];
                *(float4*)(dst + t0) = v;
            }
        }
    }
}

// ---- split weights to bf16 hi/lo ----
__global__ void kW(const float* __restrict__ qw, const float* __restrict__ pw) {
    int i = blockIdx.x * 256 + threadIdx.x;
    if (i < NO3*128) {
        __nv_bfloat16 h, l; split_bf(qw[i], h, l);
        g_wqhb[i] = h; g_wqlb[i] = l;
    }
    if (i < 128*128) {
        __nv_bfloat16 h, l; split_bf(pw[i], h, l);
        g_wphb[i] = h; g_wplb[i] = l;
    }
}

// ---- x [b][cf][t] -> g_xt [b][t][cf] ----
__global__ void k0(const float* __restrict__ x) {
    __shared__ float tl[32][33];
    int b = blockIdx.z, t0 = blockIdx.x*32, r0 = blockIdx.y*32;
    const float* xb = x + (size_t)b*CF*TTT;
    for (int i = threadIdx.y; i < 32; i += 8)
        tl[i][threadIdx.x] = xb[(size_t)(r0+i)*TTT + t0 + threadIdx.x];
    __syncthreads();
    float* d = g_xt + (size_t)b*TTT*CF;
    for (int i = threadIdx.y; i < 32; i += 8)
        d[(size_t)(t0+i)*CF + r0 + threadIdx.x] = tl[threadIdx.x][i];
}

// ==== k1: QKV conv (mma, cp.async W pipeline) + PReLU + LN + head scatter ====
// smem: sA hi/lo [0,34816); W double-buf [34816, 34816+2*69632); sY overlaps W.
#define K1_SMEM 174080
__global__ __launch_bounds__(256) void k1(
    const float* __restrict__ bias, const float* __restrict__ alp,
    const float* __restrict__ gam,  const float* __restrict__ bet)
{
    extern __shared__ __align__(16) uint8_t sm1[];
    __nv_bfloat16* sAh = (__nv_bfloat16*)(sm1);
    __nv_bfloat16* sAl = (__nv_bfloat16*)(sm1 + 17408);
    float* sY = (float*)(sm1 + 34816);
    __shared__ float r1[256], r2[256];
    uint32_t su = smem_u32(sm1);
    uint32_t uAh = su, uAl = su + 17408;

    int tid = threadIdx.x, lane = tid & 31, wid = tid >> 5;
    int wm = wid >> 2, wn = wid & 3;
    int t = blockIdx.x, b = blockIdx.y;

    auto stageW = [&](int buf, int nc) {
        int r = tid >> 1, hf = tid & 1;
        const uint4* sh = (const uint4*)(g_wqhb + nc*16384) + r*16 + hf*8;
        const uint4* sl = (const uint4*)(g_wqlb + nc*16384) + r*16 + hf*8;
        uint32_t dh = su + 34816 + buf*69632 + (uint32_t)(r*SROWK*2 + hf*128);
        #pragma unroll
        for (int j = 0; j < 8; ++j) {
            cpa16(dh + j*16,         sh + j);
            cpa16(dh + 34816 + j*16, sl + j);
        }
    };

    stageW(0, 0); CPA_COMMIT();

    // load x row [c*64+f], convert to A[f][c] hi/lo
    const float4* xr = (const float4*)(g_xt + ((size_t)b*TTT + t)*CF);
    #pragma unroll
    for (int k = 0; k < 8; ++k) {
        int i4 = tid + k*256;
        float4 v = xr[i4];
        int c = i4 >> 4, f0 = (i4 & 15) * 4;
        float vv[4] = {v.x, v.y, v.z, v.w};
        #pragma unroll
        for (int j = 0; j < 4; ++j) {
            __nv_bfloat16 h, l; split_bf(vv[j], h, l);
            sAh[(f0+j)*SROWK + c] = h;
            sAl[(f0+j)*SROWK + c] = l;
        }
    }

    float acc[3][2][4][4];
    #pragma unroll
    for (int a = 0; a < 3; ++a)
        #pragma unroll
        for (int i = 0; i < 2; ++i)
            #pragma unroll
            for (int j = 0; j < 4; ++j)
                #pragma unroll
                for (int q = 0; q < 4; ++q) acc[a][i][j][q] = 0.f;

    uint32_t aoff = (uint32_t)(((wm*32 + (lane & 15))*SROWK + (lane >> 4)*8) * 2);
    uint32_t boff = (uint32_t)(((wn*32 + ((lane & 7) + ((lane >> 4) << 3)))*SROWK + ((lane >> 3) & 1)*8) * 2);

    #pragma unroll
    for (int nc = 0; nc < 3; ++nc) {
        if (nc < 2) { stageW((nc+1)&1, nc+1); CPA_COMMIT(); cpa_wait<1>(); }
        else        { cpa_wait<0>(); }
        __syncthreads();
        uint32_t uWh = su + 34816 + (nc&1)*69632, uWl = uWh + 34816;
        #pragma unroll
        for (int kk = 0; kk < 8; ++kk) {
            uint32_t bhf[4][2], blf[4][2];
            #pragma unroll
            for (int ng = 0; ng < 2; ++ng) {
                uint32_t r4[4];
                ldsm4(r4, uWh + boff + ng*(16*SROWK*2) + kk*32);
                bhf[ng*2][0] = r4[0]; bhf[ng*2][1] = r4[1];
                bhf[ng*2+1][0] = r4[2]; bhf[ng*2+1][1] = r4[3];
                ldsm4(r4, uWl + boff + ng*(16*SROWK*2) + kk*32);
                blf[ng*2][0] = r4[0]; blf[ng*2][1] = r4[1];
                blf[ng*2+1][0] = r4[2]; blf[ng*2+1][1] = r4[3];
            }
            #pragma unroll
            for (int mf = 0; mf < 2; ++mf) {
                uint32_t ah[4], al[4];
                ldsm4(ah, uAh + aoff + mf*(16*SROWK*2) + kk*32);
                ldsm4(al, uAl + aoff + mf*(16*SROWK*2) + kk*32);
                #pragma unroll
                for (int nf = 0; nf < 4; ++nf) {
                    mmabf(acc[nc][mf][nf], ah, bhf[nf]);
                    mmabf(acc[nc][mf][nf], ah, blf[nf]);
                    mmabf(acc[nc][mf][nf], al, bhf[nf]);
                }
            }
        }
        __syncthreads();
    }

    float alpha = alp[0];
    float ls = 0.f, lq = 0.f;
    #pragma unroll
    for (int nc = 0; nc < 3; ++nc)
        #pragma unroll
        for (int mf = 0; mf < 2; ++mf)
            #pragma unroll
            for (int nf = 0; nf < 4; ++nf) {
                int o0 = nc*128 + wn*32 + nf*8 + (lane & 3)*2;
                float b0 = bias[o0], b1 = bias[o0+1];
                #pragma unroll
                for (int h = 0; h < 2; ++h) {
                    float v0 = acc[nc][mf][nf][2*h] + b0;
                    float v1 = acc[nc][mf][nf][2*h+1] + b1;
                    v0 = v0 >= 0.f ? v0 : alpha*v0;
                    v1 = v1 >= 0.f ? v1 : alpha*v1;
                    acc[nc][mf][nf][2*h] = v0; acc[nc][mf][nf][2*h+1] = v1;
                    ls += v0 + v1; lq += v0*v0 + v1*v1;
                }
            }
    r1[tid] = ls; r2[tid] = lq;
    __syncthreads();
    for (int s = 128; s > 0; s >>= 1) {
        if (tid < s) { r1[tid] += r1[tid+s]; r2[tid] += r2[tid+s]; }
        __syncthreads();
    }
    const float invN = 1.f / (float)(NO3*FFQ);
    float mu = r1[0]*invN, var = r2[0]*invN - mu*mu;
    float rstd = rsqrtf(var + EPSV);

    #pragma unroll
    for (int nc = 0; nc < 3; ++nc)
        #pragma unroll
        for (int mf = 0; mf < 2; ++mf)
            #pragma unroll
            for (int nf = 0; nf < 4; ++nf) {
                int o0 = nc*128 + wn*32 + nf*8 + (lane & 3)*2;
                #pragma unroll
                for (int h = 0; h < 2; ++h) {
                    int f = wm*32 + mf*16 + h*8 + (lane >> 2);
                    int gi0 = o0*64 + f, gi1 = gi0 + 64;
                    sY[gi0] = (acc[nc][mf][nf][2*h]   - mu)*rstd*gam[gi0] + bet[gi0];
                    sY[gi1] = (acc[nc][mf][nf][2*h+1] - mu)*rstd*gam[gi1] + bet[gi1];
                }
            }
    __syncthreads();

    int to = tid >> 3, tf = tid & 7;
    #pragma unroll
    for (int r = 0; r < 12; ++r) {
        int o = to*12 + r;
        int h = o / 48, rem = o % 48;
        int which = rem >> 4, dc = rem & 15;
        size_t base = (((size_t)b*NHH + h)*TTT + t)*HDD + dc*FFQ + (tf << 3);
        float ov[8];
        *(float4*)(ov)     = *(const float4*)(sY + o*64 + (tf << 3));
        *(float4*)(ov + 4) = *(const float4*)(sY + o*64 + (tf << 3) + 4);
        if (which == 2) {
            *(float4*)(g_v + base)     = *(float4*)(ov);
            *(float4*)(g_v + base + 4) = *(float4*)(ov + 4);
        } else {
            __nv_bfloat16* dh = (which == 0) ? g_qh : g_kh;
            __nv_bfloat16* dl = (which == 0) ? g_ql : g_kl;
            uint32_t hp[4], lp[4];
            #pragma unroll
            for (int p = 0; p < 4; ++p) {
                __nv_bfloat16 h0, l0, h1, l1;
                split_bf(ov[2*p], h0, l0);
                split_bf(ov[2*p+1], h1, l1);
                hp[p] = (uint32_t)__bfloat16_as_ushort(h0) | ((uint32_t)__bfloat16_as_ushort(h1) << 16);
                lp[p] = (uint32_t)__bfloat16_as_ushort(l0) | ((uint32_t)__bfloat16_as_ushort(l1) << 16);
            }
            *(uint4*)(dh + base) = *(uint4*)hp;
            *(uint4*)(dl + base) = *(uint4*)lp;
        }
    }
}

// ---- V transpose + split ----
__global__ void k1v() {
    __shared__ float tl[32][33];
    int bh = blockIdx.z, t0 = blockIdx.x*32, d0 = blockIdx.y*32;
    const float* src = g_v + (size_t)bh*TTT*HDD;
    for (int i = threadIdx.y; i < 32; i += 8)
        tl[i][threadIdx.x] = src[(size_t)(t0+i)*HDD + d0 + threadIdx.x];
    __syncthreads();
    size_t ob = (size_t)bh*HDD*TTT;
    for (int i = threadIdx.y; i < 32; i += 8) {
        __nv_bfloat16 h, l; split_bf(tl[threadIdx.x][i], h, l);
        size_t o = ob + (size_t)(d0+i)*TTT + t0 + threadIdx.x;
        g_vth[o] = h; g_vtl[o] = l;
    }
}

// ---- k2a: S = QK^T /32 (causal) ----
__global__ __launch_bounds__(256) void k2a() {
    int kt = blockIdx.x, qt = blockIdx.y, bh = blockIdx.z;
    if (kt > qt) return;
    const __nv_bfloat16* Ah = g_qh + ((size_t)bh*TTT + qt*128)*HDD;
    const __nv_bfloat16* Al = g_ql + ((size_t)bh*TTT + qt*128)*HDD;
    const __nv_bfloat16* Bh = g_kh + ((size_t)bh*TTT + kt*128)*HDD;
    const __nv_bfloat16* Bl = g_kl + ((size_t)bh*TTT + kt*128)*HDD;
    float* outp = g_s + (size_t)bh*TTT*TTT + (size_t)(qt*128)*TTT + kt*128;
    mma_core<0>(Ah, Al, HDD, Bh, Bl, HDD, HDD, outp, TTT, qt*128, kt*128, 0.03125f, 0, 0, 0);
}

// ---- k2b: prefix softmax -> P hi/lo bf16 ----
__global__ __launch_bounds__(256) void k2b() {
    int qi = blockIdx.x, bh = blockIdx.y;
    int n = (qi & ~127) + 128;
    const float* row = g_s + ((size_t)bh*TTT + qi)*TTT;
    __shared__ float red[256];
    int tid = threadIdx.x;
    float v0 = (tid < n)     ? row[tid]     : -1e30f;
    float v1 = (tid+256 < n) ? row[tid+256] : -1e30f;
    red[tid] = fmaxf(v0, v1); __syncthreads();
    for (int s = 128; s > 0; s >>= 1) {
        if (tid < s) red[tid] = fmaxf(red[tid], red[tid+s]);
        __syncthreads();
    }
    float m = red[0]; __syncthreads();
    float e0 = __expf(v0 - m), e1 = __expf(v1 - m);
    red[tid] = e0 + e1; __syncthreads();
    for (int s = 128; s > 0; s >>= 1) {
        if (tid < s) red[tid] += red[tid+s];
        __syncthreads();
    }
    float inv = 1.f / red[0];
    __nv_bfloat16* ph = g_ph + ((size_t)bh*TTT + qi)*TTT;
    __nv_bfloat16* pl = g_pl + ((size_t)bh*TTT + qi)*TTT;
    if (tid < n) {
        float p = e0 * inv;
        __nv_bfloat16 h, l; split_bf(p, h, l);
        ph[tid] = h; pl[tid] = l;
    }
    if (tid + 256 < n) {
        float p = e1 * inv;
        __nv_bfloat16 h, l; split_bf(p, h, l);
        ph[tid+256] = h; pl[tid+256] = l;
    }
}

// ---- k2c: ctx = P @ V, fused transpose into g_c ----
__global__ __launch_bounds__(256) void k2c() {
    int dt = blockIdx.x, qt = blockIdx.y, bh = blockIdx.z;
    const __nv_bfloat16* Ah = g_ph  + ((size_t)bh*TTT + qt*128)*TTT;
    const __nv_bfloat16* Al = g_pl  + ((size_t)bh*TTT + qt*128)*TTT;
    const __nv_bfloat16* Bh = g_vth + ((size_t)bh*HDD + dt*128)*TTT;
    const __nv_bfloat16* Bl = g_vtl + ((size_t)bh*HDD + dt*128)*TTT;
    mma_core<1>(Ah, Al, TTT, Bh, Bl, TTT, (qt + 1)*128, nullptr, 0, 0, 0, 1.f, bh, dt, qt);
}

// ==== k4: proj conv (mma, cp.async W) + PReLU + LN ====
// smem: sA hi/lo [0,34816); W [34816,104448); sY overlaps W.
#define K4_SMEM 104448
__global__ __launch_bounds__(256) void k4(
    const float* __restrict__ bias, const float* __restrict__ alp,
    const float* __restrict__ gam,  const float* __restrict__ bet)
{
    extern __shared__ __align__(16) uint8_t sm4[];
    __nv_bfloat16* sAh = (__nv_bfloat16*)(sm4);
    __nv_bfloat16* sAl = (__nv_bfloat16*)(sm4 + 17408);
    float* sY = (float*)(sm4 + 34816);
    __shared__ float r1[256], r2[256];
    uint32_t su = smem_u32(sm4);
    uint32_t uAh = su, uAl = su + 17408;
    uint32_t uWh = su + 34816, uWl = su + 34816 + 34816;

    int tid = threadIdx.x, lane = tid & 31, wid = tid >> 5;
    int wm = wid >> 2, wn = wid & 3;
    int t2 = blockIdx.x, b = blockIdx.y;

    // issue W cp.async first (overlaps A gather)
    {
        int r = tid >> 1, hf = tid & 1;
        const uint4* sh = (const uint4*)g_wphb + r*16 + hf*8;
        const uint4* sl = (const uint4*)g_wplb + r*16 + hf*8;
        uint32_t dh = uWh + (uint32_t)(r*SROWK*2 + hf*128);
        #pragma unroll
        for (int j = 0; j < 8; ++j) {
            cpa16(dh + j*16,         sh + j);
            cpa16(dh + 34816 + j*16, sl + j);
        }
        CPA_COMMIT();
    }

    // gather A[f][c] from g_c[(b*128+c)][t2][f]
    {
        int c = tid >> 1, half = tid & 1;
        const float4* sp = (const float4*)(g_c + (((size_t)(b*128 + c))*TTT + t2)*FFQ + half*32);
        #pragma unroll
        for (int j = 0; j < 8; ++j) {
            float4 v = sp[j];
            int f0 = half*32 + j*4;
            float vv[4] = {v.x, v.y, v.z, v.w};
            #pragma unroll
            for (int jj = 0; jj < 4; ++jj) {
                __nv_bfloat16 h, l; split_bf(vv[jj], h, l);
                sAh[(f0+jj)*SROWK + c] = h;
                sAl[(f0+jj)*SROWK + c] = l;
            }
        }
    }
    cpa_wait<0>();
    __syncthreads();

    float acc[2][4][4];
    #pragma unroll
    for (int i = 0; i < 2; ++i)
        #pragma unroll
        for (int j = 0; j < 4; ++j)
            #pragma unroll
            for (int q = 0; q < 4; ++q) acc[i][j][q] = 0.f;

    uint32_t aoff = (uint32_t)(((wm*32 + (lane & 15))*SROWK + (lane >> 4)*8) * 2);
    uint32_t boff = (uint32_t)(((wn*32 + ((lane & 7) + ((lane >> 4) << 3)))*SROWK + ((lane >> 3) & 1)*8) * 2);

    #pragma unroll
    for (int kk = 0; kk < 8; ++kk) {
        uint32_t bhf[4][2], blf[4][2];
        #pragma unroll
        for (int ng = 0; ng < 2; ++ng) {
            uint32_t r4[4];
            ldsm4(r4, uWh + boff + ng*(16*SROWK*2) + kk*32);
            bhf[ng*2][0] = r4[0]; bhf[ng*2][1] = r4[1];
            bhf[ng*2+1][0] = r4[2]; bhf[ng*2+1][1] = r4[3];
            ldsm4(r4, uWl + boff + ng*(16*SROWK*2) + kk*32);
            blf[ng*2][0] = r4[0]; blf[ng*2][1] = r4[1];
            blf[ng*2+1][0] = r4[2]; blf[ng*2+1][1] = r4[3];
        }
        #pragma unroll
        for (int mf = 0; mf < 2; ++mf) {
            uint32_t ah[4], al[4];
            ldsm4(ah, uAh + aoff + mf*(16*SROWK*2) + kk*32);
            ldsm4(al, uAl + aoff + mf*(16*SROWK*2) + kk*32);
            #pragma unroll
            for (int nf = 0; nf < 4; ++nf) {
                mmabf(acc[mf][nf], ah, bhf[nf]);
                mmabf(acc[mf][nf], ah, blf[nf]);
                mmabf(acc[mf][nf], al, bhf[nf]);
            }
        }
    }

    float alpha = alp[0];
    float ls = 0.f, lq = 0.f;
    #pragma unroll
    for (int mf = 0; mf < 2; ++mf)
        #pragma unroll
        for (int nf = 0; nf < 4; ++nf) {
            int o0 = wn*32 + nf*8 + (lane & 3)*2;
            float b0 = bias[o0], b1 = bias[o0+1];
            #pragma unroll
            for (int h = 0; h < 2; ++h) {
                float v0 = acc[mf][nf][2*h] + b0;
                float v1 = acc[mf][nf][2*h+1] + b1;
                v0 = v0 >= 0.f ? v0 : alpha*v0;
                v1 = v1 >= 0.f ? v1 : alpha*v1;
                acc[mf][nf][2*h] = v0; acc[mf][nf][2*h+1] = v1;
                ls += v0 + v1; lq += v0*v0 + v1*v1;
            }
        }
    r1[tid] = ls; r2[tid] = lq;
    __syncthreads();
    for (int s = 128; s > 0; s >>= 1) {
        if (tid < s) { r1[tid] += r1[tid+s]; r2[tid] += r2[tid+s]; }
        __syncthreads();
    }
    const float invN = 1.f / (float)CF;
    float mu = r1[0]*invN, var = r2[0]*invN - mu*mu;
    float rstd = rsqrtf(var + EPSV);

    __syncthreads();   // all ldsm reads of W region done before sY overwrite
    #pragma unroll
    for (int mf = 0; mf < 2; ++mf)
        #pragma unroll
        for (int nf = 0; nf < 4; ++nf) {
            int o0 = wn*32 + nf*8 + (lane & 3)*2;
            #pragma unroll
            for (int h = 0; h < 2; ++h) {
                int f = wm*32 + mf*16 + h*8 + (lane >> 2);
                int gi0 = o0*64 + f, gi1 = gi0 + 64;
                sY[gi0] = (acc[mf][nf][2*h]   - mu)*rstd*gam[gi0] + bet[gi0];
                sY[gi1] = (acc[mf][nf][2*h+1] - mu)*rstd*gam[gi1] + bet[gi1];
            }
        }
    __syncthreads();

    float* yrow = g_y + ((size_t)b*TTT + t2)*CF;
    const float4* sY4 = (const float4*)sY;
    float4* yr4 = (float4*)yrow;
    #pragma unroll
    for (int k = 0; k < 8; ++k) yr4[tid + k*256] = sY4[tid + k*256];
}

// ---- g_y [b][t2][cf] -> out [b][cf][t2] ----
__global__ void k5(float* __restrict__ out) {
    __shared__ float tl[32][33];
    int b = blockIdx.z, t0 = blockIdx.x*32, r0 = blockIdx.y*32;
    const float* s = g_y + (size_t)b*TTT*CF;
    for (int i = threadIdx.y; i < 32; i += 8)
        tl[i][threadIdx.x] = s[(size_t)(t0+i)*CF + r0 + threadIdx.x];
    __syncthreads();
    float* d = out + (size_t)b*CF*TTT;
    for (int i = threadIdx.y; i < 32; i += 8)
        d[(size_t)(r0+i)*TTT + t0 + threadIdx.x] = tl[threadIdx.x][i];
}

extern "C" void kernel_launch(void* const* d_in, const int* in_sizes, int n_in,
                              void* d_out, int out_size) {
    const float* x   = (const float*)d_in[0];
    const float* qw  = (const float*)d_in[1];
    const float* qb  = (const float*)d_in[2];
    const float* qa  = (const float*)d_in[3];
    const float* qg  = (const float*)d_in[4];
    const float* qbe = (const float*)d_in[5];
    const float* pw  = (const float*)d_in[6];
    const float* pb  = (const float*)d_in[7];
    const float* pa  = (const float*)d_in[8];
    const float* pg  = (const float*)d_in[9];
    const float* pbe = (const float*)d_in[10];
    float* out = (float*)d_out;

    cudaFuncSetAttribute(k1,  cudaFuncAttributeMaxDynamicSharedMemorySize, K1_SMEM);
    cudaFuncSetAttribute(k2a, cudaFuncAttributeMaxDynamicSharedMemorySize, SMEMSZ_AT);
    cudaFuncSetAttribute(k2c, cudaFuncAttributeMaxDynamicSharedMemorySize, SMEMSZ_AT);
    cudaFuncSetAttribute(k4,  cudaFuncAttributeMaxDynamicSharedMemorySize, K4_SMEM);

    dim3 tb(32, 8);
    kW <<<192, 256>>>(qw, pw);
    k0 <<<dim3(16, 256, 4), tb>>>(x);
    k1 <<<dim3(512, 4), 256, K1_SMEM>>>(qb, qa, qg, qbe);
    k1v<<<dim3(16, 32, 32), tb>>>();
    k2a<<<dim3(4, 4, 32), 256, SMEMSZ_AT>>>();
    k2b<<<dim3(512, 32), 256>>>();
    k2c<<<dim3(8, 4, 32), 256, SMEMSZ_AT>>>();
    k4 <<<dim3(512, 4), 256, K4_SMEM>>>(pb, pa, pg, pbe);
    k5 <<<dim3(16, 256, 4), tb>>>(out);
}

// round 9
// speedup vs baseline: 1.0648x; 1.0648x over previous
#include <cuda_runtime.h>
#include <cuda_bf16.h>
#include <cstdint>
#include <cstddef>

#define BB 4
#define NO3 384
#define FFQ 64
#define TTT 512
#define NHH 8
#define HDD 1024
#define CF 8192
#define EPSV 1e-5f

// ---------------- scratch ----------------
__device__ float g_xt [BB*TTT*CF];
__device__ float g_v  [BB*NHH*TTT*HDD];
__device__ float g_s  [BB*NHH*TTT*TTT];
__device__ float g_c  [BB*128*TTT*FFQ];
__device__ float g_y  [BB*TTT*CF];
__device__ __nv_bfloat16 g_wqhb[NO3*128], g_wqlb[NO3*128];
__device__ __nv_bfloat16 g_wphb[128*128], g_wplb[128*128];
__device__ __nv_bfloat16 g_qh[BB*NHH*TTT*HDD];
__device__ __nv_bfloat16 g_ql[BB*NHH*TTT*HDD];
__device__ __nv_bfloat16 g_kh[BB*NHH*TTT*HDD];
__device__ __nv_bfloat16 g_kl[BB*NHH*TTT*HDD];
__device__ __nv_bfloat16 g_vth[BB*NHH*HDD*TTT];
__device__ __nv_bfloat16 g_vtl[BB*NHH*HDD*TTT];
__device__ __nv_bfloat16 g_ph[BB*NHH*TTT*TTT];
__device__ __nv_bfloat16 g_pl[BB*NHH*TTT*TTT];

// ---------------- helpers ----------------
__device__ __forceinline__ uint32_t smem_u32(const void* p) {
    uint32_t a;
    asm("{ .reg .u64 t; cvta.to.shared.u64 t, %1; cvt.u32.u64 %0, t; }" : "=r"(a) : "l"(p));
    return a;
}
__device__ __forceinline__ void ldsm4(uint32_t* r, uint32_t a) {
    asm volatile("ldmatrix.sync.aligned.m8n8.x4.shared.b16 {%0,%1,%2,%3}, [%4];"
        : "=r"(r[0]), "=r"(r[1]), "=r"(r[2]), "=r"(r[3]) : "r"(a));
}
__device__ __forceinline__ void mmabf(float* c, const uint32_t* a, const uint32_t* b) {
    asm volatile("mma.sync.aligned.m16n8k16.row.col.f32.bf16.bf16.f32 "
        "{%0,%1,%2,%3}, {%4,%5,%6,%7}, {%8,%9}, {%0,%1,%2,%3};"
        : "+f"(c[0]), "+f"(c[1]), "+f"(c[2]), "+f"(c[3])
        : "r"(a[0]), "r"(a[1]), "r"(a[2]), "r"(a[3]), "r"(b[0]), "r"(b[1]));
}
__device__ __forceinline__ void split_bf(float f, __nv_bfloat16& h, __nv_bfloat16& l) {
    h = __float2bfloat16(f);
    l = __float2bfloat16(f - __bfloat162float(h));
}
__device__ __forceinline__ void cpa16(uint32_t s, const void* g) {
    asm volatile("cp.async.cg.shared.global [%0], [%1], 16;" :: "r"(s), "l"(g));
}
#define CPA_COMMIT() asm volatile("cp.async.commit_group;" ::: "memory")
template<int N> __device__ __forceinline__ void cpa_wait() {
    asm volatile("cp.async.wait_group %0;" :: "n"(N) : "memory");
}

// attention tiles: 128x64 bf16, stride 72 (R7 config: 73728 B -> 2 CTAs/SM)
#define SROW 72
#define STILE (128*SROW)
#define SMEMSZ (4*STILE*2)
// conv tiles: stride 136 elems
#define SROWK 136

// ======== R7 attention GEMM core (synchronous staging, 2 CTAs/SM) ========
// MODE 0: masked+scaled direct store (k2a). MODE 1: transposed store into g_c (k2c, fused k3).
template<int MODE>
__device__ __forceinline__ void mma_core(
    const __nv_bfloat16* __restrict__ Ah, const __nv_bfloat16* __restrict__ Al, int lda,
    const __nv_bfloat16* __restrict__ Bh, const __nv_bfloat16* __restrict__ Bl, int ldb,
    int kmax, float* __restrict__ outp, int ldo, int row0, int col0, float scale,
    int bh, int dt, int qt)
{
    extern __shared__ __align__(16) __nv_bfloat16 sm[];
    __nv_bfloat16* sAh = sm;
    __nv_bfloat16* sAl = sm + STILE;
    __nv_bfloat16* sBh = sm + 2*STILE;
    __nv_bfloat16* sBl = sm + 3*STILE;
    uint32_t uAh = smem_u32(sAh), uAl = smem_u32(sAl);
    uint32_t uBh = smem_u32(sBh), uBl = smem_u32(sBl);

    int tid = threadIdx.x, lane = tid & 31, wid = tid >> 5;
    int wm = wid >> 2, wn = wid & 3;

    float acc[4][4][4];
    #pragma unroll
    for (int i = 0; i < 4; ++i)
        #pragma unroll
        for (int j = 0; j < 4; ++j)
            #pragma unroll
            for (int q = 0; q < 4; ++q) acc[i][j][q] = 0.f;

    uint32_t aoff = (uint32_t)(((wm*64 + (lane & 15))*SROW + (lane >> 4)*8) * 2);
    uint32_t boff = (uint32_t)(((wn*32 + ((lane & 7) + ((lane >> 4) << 3)))*SROW + ((lane >> 3) & 1)*8) * 2);

    for (int k0 = 0; k0 < kmax; k0 += 64) {
        __syncthreads();
        #pragma unroll
        for (int j = 0; j < 4; ++j) {
            int ii = j*256 + tid;
            int r = ii >> 3, c = (ii & 7) << 3;
            *(uint4*)(sAh + r*SROW + c) = *(const uint4*)(Ah + (size_t)r*lda + k0 + c);
            *(uint4*)(sAl + r*SROW + c) = *(const uint4*)(Al + (size_t)r*lda + k0 + c);
            *(uint4*)(sBh + r*SROW + c) = *(const uint4*)(Bh + (size_t)r*ldb + k0 + c);
            *(uint4*)(sBl + r*SROW + c) = *(const uint4*)(Bl + (size_t)r*ldb + k0 + c);
        }
        __syncthreads();
        #pragma unroll
        for (int kk = 0; kk < 4; ++kk) {
            uint32_t bh_[4][2], bl_[4][2];
            #pragma unroll
            for (int ng = 0; ng < 2; ++ng) {
                uint32_t r4[4];
                ldsm4(r4, uBh + boff + ng*(16*SROW*2) + kk*32);
                bh_[ng*2][0] = r4[0]; bh_[ng*2][1] = r4[1];
                bh_[ng*2+1][0] = r4[2]; bh_[ng*2+1][1] = r4[3];
                ldsm4(r4, uBl + boff + ng*(16*SROW*2) + kk*32);
                bl_[ng*2][0] = r4[0]; bl_[ng*2][1] = r4[1];
                bl_[ng*2+1][0] = r4[2]; bl_[ng*2+1][1] = r4[3];
            }
            #pragma unroll
            for (int mf = 0; mf < 4; ++mf) {
                uint32_t ah[4], al[4];
                ldsm4(ah, uAh + aoff + mf*(16*SROW*2) + kk*32);
                ldsm4(al, uAl + aoff + mf*(16*SROW*2) + kk*32);
                #pragma unroll
                for (int nf = 0; nf < 4; ++nf) {
                    mmabf(acc[mf][nf], ah, bh_[nf]);
                    mmabf(acc[mf][nf], ah, bl_[nf]);
                    mmabf(acc[mf][nf], al, bh_[nf]);
                }
            }
        }
    }

    int rloc0 = wm*64 + (lane >> 2);
    int cloc  = wn*32 + (lane & 3)*2;
    if (MODE == 0) {
        #pragma unroll
        for (int mf = 0; mf < 4; ++mf) {
            #pragma unroll
            for (int nf = 0; nf < 4; ++nf) {
                int cc = cloc + nf*8;
                int cg = col0 + cc;
                #pragma unroll
                for (int h = 0; h < 2; ++h) {
                    int rl = rloc0 + mf*16 + h*8;
                    int rg = row0 + rl;
                    float v0 = acc[mf][nf][2*h], v1 = acc[mf][nf][2*h+1];
                    v0 = (cg     <= rg) ? v0*scale : -1e30f;
                    v1 = (cg + 1 <= rg) ? v1*scale : -1e30f;
                    *(float2*)(outp + (size_t)rl*ldo + cc) = make_float2(v0, v1);
                }
            }
        }
    } else {
        // fused k3: park tile [t][d] in smem (stride 132), then write [d][t] coalesced to g_c
        __syncthreads();    // all ldsm reads done before smem reuse
        float* Y = (float*)sm;
        #pragma unroll
        for (int mf = 0; mf < 4; ++mf)
            #pragma unroll
            for (int nf = 0; nf < 4; ++nf) {
                int cc = cloc + nf*8;
                #pragma unroll
                for (int h = 0; h < 2; ++h) {
                    int rl = rloc0 + mf*16 + h*8;
                    *(float2*)(Y + rl*132 + cc) = make_float2(acc[mf][nf][2*h], acc[mf][nf][2*h+1]);
                }
            }
        __syncthreads();
        size_t cb = (size_t)(bh*16 + dt*2)*32768 + qt*128;
        int tq = tid & 3;
        #pragma unroll
        for (int pass = 0; pass < 2; ++pass) {
            int dcol = (tid >> 2) + pass*64;
            float* dst = g_c + cb + (size_t)(dcol >> 6)*32768 + (dcol & 63)*512;
            #pragma unroll
            for (int j = 0; j < 8; ++j) {
                int t0 = tq*4 + j*16;
                float4 v;
                v.x = Y[(t0+0)*132 + dcol];
                v.y = Y[(t0+1)*132 + dcol];
                v.z = Y[(t0+2)*132 + dcol];
                v.w = Y[(t0+3)*132 + dcol];
                *(float4*)(dst + t0) = v;
            }
        }
    }
}

// ---- split weights to bf16 hi/lo ----
__global__ void kW(const float* __restrict__ qw, const float* __restrict__ pw) {
    int i = blockIdx.x * 256 + threadIdx.x;
    if (i < NO3*128) {
        __nv_bfloat16 h, l; split_bf(qw[i], h, l);
        g_wqhb[i] = h; g_wqlb[i] = l;
    }
    if (i < 128*128) {
        __nv_bfloat16 h, l; split_bf(pw[i], h, l);
        g_wphb[i] = h; g_wplb[i] = l;
    }
}

// ---- x [b][cf][t] -> g_xt [b][t][cf] ----
__global__ void k0(const float* __restrict__ x) {
    __shared__ float tl[32][33];
    int b = blockIdx.z, t0 = blockIdx.x*32, r0 = blockIdx.y*32;
    const float* xb = x + (size_t)b*CF*TTT;
    for (int i = threadIdx.y; i < 32; i += 8)
        tl[i][threadIdx.x] = xb[(size_t)(r0+i)*TTT + t0 + threadIdx.x];
    __syncthreads();
    float* d = g_xt + (size_t)b*TTT*CF;
    for (int i = threadIdx.y; i < 32; i += 8)
        d[(size_t)(t0+i)*CF + r0 + threadIdx.x] = tl[threadIdx.x][i];
}

// ==== k1: QKV conv (mma, cp.async W pipeline) + PReLU + LN + head scatter ====
#define K1_SMEM 174080
__global__ __launch_bounds__(256) void k1(
    const float* __restrict__ bias, const float* __restrict__ alp,
    const float* __restrict__ gam,  const float* __restrict__ bet)
{
    extern __shared__ __align__(16) uint8_t sm1[];
    __nv_bfloat16* sAh = (__nv_bfloat16*)(sm1);
    __nv_bfloat16* sAl = (__nv_bfloat16*)(sm1 + 17408);
    float* sY = (float*)(sm1 + 34816);
    __shared__ float r1[256], r2[256];
    uint32_t su = smem_u32(sm1);
    uint32_t uAh = su, uAl = su + 17408;

    int tid = threadIdx.x, lane = tid & 31, wid = tid >> 5;
    int wm = wid >> 2, wn = wid & 3;
    int t = blockIdx.x, b = blockIdx.y;

    auto stageW = [&](int buf, int nc) {
        int r = tid >> 1, hf = tid & 1;
        const uint4* sh = (const uint4*)(g_wqhb + nc*16384) + r*16 + hf*8;
        const uint4* sl = (const uint4*)(g_wqlb + nc*16384) + r*16 + hf*8;
        uint32_t dh = su + 34816 + buf*69632 + (uint32_t)(r*SROWK*2 + hf*128);
        #pragma unroll
        for (int j = 0; j < 8; ++j) {
            cpa16(dh + j*16,         sh + j);
            cpa16(dh + 34816 + j*16, sl + j);
        }
    };

    stageW(0, 0); CPA_COMMIT();

    const float4* xr = (const float4*)(g_xt + ((size_t)b*TTT + t)*CF);
    #pragma unroll
    for (int k = 0; k < 8; ++k) {
        int i4 = tid + k*256;
        float4 v = xr[i4];
        int c = i4 >> 4, f0 = (i4 & 15) * 4;
        float vv[4] = {v.x, v.y, v.z, v.w};
        #pragma unroll
        for (int j = 0; j < 4; ++j) {
            __nv_bfloat16 h, l; split_bf(vv[j], h, l);
            sAh[(f0+j)*SROWK + c] = h;
            sAl[(f0+j)*SROWK + c] = l;
        }
    }

    float acc[3][2][4][4];
    #pragma unroll
    for (int a = 0; a < 3; ++a)
        #pragma unroll
        for (int i = 0; i < 2; ++i)
            #pragma unroll
            for (int j = 0; j < 4; ++j)
                #pragma unroll
                for (int q = 0; q < 4; ++q) acc[a][i][j][q] = 0.f;

    uint32_t aoff = (uint32_t)(((wm*32 + (lane & 15))*SROWK + (lane >> 4)*8) * 2);
    uint32_t boff = (uint32_t)(((wn*32 + ((lane & 7) + ((lane >> 4) << 3)))*SROWK + ((lane >> 3) & 1)*8) * 2);

    #pragma unroll
    for (int nc = 0; nc < 3; ++nc) {
        if (nc < 2) { stageW((nc+1)&1, nc+1); CPA_COMMIT(); cpa_wait<1>(); }
        else        { cpa_wait<0>(); }
        __syncthreads();
        uint32_t uWh = su + 34816 + (nc&1)*69632, uWl = uWh + 34816;
        #pragma unroll
        for (int kk = 0; kk < 8; ++kk) {
            uint32_t bhf[4][2], blf[4][2];
            #pragma unroll
            for (int ng = 0; ng < 2; ++ng) {
                uint32_t r4[4];
                ldsm4(r4, uWh + boff + ng*(16*SROWK*2) + kk*32);
                bhf[ng*2][0] = r4[0]; bhf[ng*2][1] = r4[1];
                bhf[ng*2+1][0] = r4[2]; bhf[ng*2+1][1] = r4[3];
                ldsm4(r4, uWl + boff + ng*(16*SROWK*2) + kk*32);
                blf[ng*2][0] = r4[0]; blf[ng*2][1] = r4[1];
                blf[ng*2+1][0] = r4[2]; blf[ng*2+1][1] = r4[3];
            }
            #pragma unroll
            for (int mf = 0; mf < 2; ++mf) {
                uint32_t ah[4], al[4];
                ldsm4(ah, uAh + aoff + mf*(16*SROWK*2) + kk*32);
                ldsm4(al, uAl + aoff + mf*(16*SROWK*2) + kk*32);
                #pragma unroll
                for (int nf = 0; nf < 4; ++nf) {
                    mmabf(acc[nc][mf][nf], ah, bhf[nf]);
                    mmabf(acc[nc][mf][nf], ah, blf[nf]);
                    mmabf(acc[nc][mf][nf], al, bhf[nf]);
                }
            }
        }
        __syncthreads();
    }

    float alpha = alp[0];
    float ls = 0.f, lq = 0.f;
    #pragma unroll
    for (int nc = 0; nc < 3; ++nc)
        #pragma unroll
        for (int mf = 0; mf < 2; ++mf)
            #pragma unroll
            for (int nf = 0; nf < 4; ++nf) {
                int o0 = nc*128 + wn*32 + nf*8 + (lane & 3)*2;
                float b0 = bias[o0], b1 = bias[o0+1];
                #pragma unroll
                for (int h = 0; h < 2; ++h) {
                    float v0 = acc[nc][mf][nf][2*h] + b0;
                    float v1 = acc[nc][mf][nf][2*h+1] + b1;
                    v0 = v0 >= 0.f ? v0 : alpha*v0;
                    v1 = v1 >= 0.f ? v1 : alpha*v1;
                    acc[nc][mf][nf][2*h] = v0; acc[nc][mf][nf][2*h+1] = v1;
                    ls += v0 + v1; lq += v0*v0 + v1*v1;
                }
            }
    r1[tid] = ls; r2[tid] = lq;
    __syncthreads();
    for (int s = 128; s > 0; s >>= 1) {
        if (tid < s) { r1[tid] += r1[tid+s]; r2[tid] += r2[tid+s]; }
        __syncthreads();
    }
    const float invN = 1.f / (float)(NO3*FFQ);
    float mu = r1[0]*invN, var = r2[0]*invN - mu*mu;
    float rstd = rsqrtf(var + EPSV);

    #pragma unroll
    for (int nc = 0; nc < 3; ++nc)
        #pragma unroll
        for (int mf = 0; mf < 2; ++mf)
            #pragma unroll
            for (int nf = 0; nf < 4; ++nf) {
                int o0 = nc*128 + wn*32 + nf*8 + (lane & 3)*2;
                #pragma unroll
                for (int h = 0; h < 2; ++h) {
                    int f = wm*32 + mf*16 + h*8 + (lane >> 2);
                    int gi0 = o0*64 + f, gi1 = gi0 + 64;
                    sY[gi0] = (acc[nc][mf][nf][2*h]   - mu)*rstd*gam[gi0] + bet[gi0];
                    sY[gi1] = (acc[nc][mf][nf][2*h+1] - mu)*rstd*gam[gi1] + bet[gi1];
                }
            }
    __syncthreads();

    int to = tid >> 3, tf = tid & 7;
    #pragma unroll
    for (int r = 0; r < 12; ++r) {
        int o = to*12 + r;
        int h = o / 48, rem = o % 48;
        int which = rem >> 4, dc = rem & 15;
        size_t base = (((size_t)b*NHH + h)*TTT + t)*HDD + dc*FFQ + (tf << 3);
        float ov[8];
        *(float4*)(ov)     = *(const float4*)(sY + o*64 + (tf << 3));
        *(float4*)(ov + 4) = *(const float4*)(sY + o*64 + (tf << 3) + 4);
        if (which == 2) {
            *(float4*)(g_v + base)     = *(float4*)(ov);
            *(float4*)(g_v + base + 4) = *(float4*)(ov + 4);
        } else {
            __nv_bfloat16* dh = (which == 0) ? g_qh : g_kh;
            __nv_bfloat16* dl = (which == 0) ? g_ql : g_kl;
            uint32_t hp[4], lp[4];
            #pragma unroll
            for (int p = 0; p < 4; ++p) {
                __nv_bfloat16 h0, l0, h1, l1;
                split_bf(ov[2*p], h0, l0);
                split_bf(ov[2*p+1], h1, l1);
                hp[p] = (uint32_t)__bfloat16_as_ushort(h0) | ((uint32_t)__bfloat16_as_ushort(h1) << 16);
                lp[p] = (uint32_t)__bfloat16_as_ushort(l0) | ((uint32_t)__bfloat16_as_ushort(l1) << 16);
            }
            *(uint4*)(dh + base) = *(uint4*)hp;
            *(uint4*)(dl + base) = *(uint4*)lp;
        }
    }
}

// ---- V transpose + split ----
__global__ void k1v() {
    __shared__ float tl[32][33];
    int bh = blockIdx.z, t0 = blockIdx.x*32, d0 = blockIdx.y*32;
    const float* src = g_v + (size_t)bh*TTT*HDD;
    for (int i = threadIdx.y; i < 32; i += 8)
        tl[i][threadIdx.x] = src[(size_t)(t0+i)*HDD + d0 + threadIdx.x];
    __syncthreads();
    size_t ob = (size_t)bh*HDD*TTT;
    for (int i = threadIdx.y; i < 32; i += 8) {
        __nv_bfloat16 h, l; split_bf(tl[threadIdx.x][i], h, l);
        size_t o = ob + (size_t)(d0+i)*TTT + t0 + threadIdx.x;
        g_vth[o] = h; g_vtl[o] = l;
    }
}

// ---- k2a: S = QK^T /32 (causal) ----
__global__ __launch_bounds__(256) void k2a() {
    int kt = blockIdx.x, qt = blockIdx.y, bh = blockIdx.z;
    if (kt > qt) return;
    const __nv_bfloat16* Ah = g_qh + ((size_t)bh*TTT + qt*128)*HDD;
    const __nv_bfloat16* Al = g_ql + ((size_t)bh*TTT + qt*128)*HDD;
    const __nv_bfloat16* Bh = g_kh + ((size_t)bh*TTT + kt*128)*HDD;
    const __nv_bfloat16* Bl = g_kl + ((size_t)bh*TTT + kt*128)*HDD;
    float* outp = g_s + (size_t)bh*TTT*TTT + (size_t)(qt*128)*TTT + kt*128;
    mma_core<0>(Ah, Al, HDD, Bh, Bl, HDD, HDD, outp, TTT, qt*128, kt*128, 0.03125f, 0, 0, 0);
}

// ---- k2b: prefix softmax -> P hi/lo bf16 ----
__global__ __launch_bounds__(256) void k2b() {
    int qi = blockIdx.x, bh = blockIdx.y;
    int n = (qi & ~127) + 128;
    const float* row = g_s + ((size_t)bh*TTT + qi)*TTT;
    __shared__ float red[256];
    int tid = threadIdx.x;
    float v0 = (tid < n)     ? row[tid]     : -1e30f;
    float v1 = (tid+256 < n) ? row[tid+256] : -1e30f;
    red[tid] = fmaxf(v0, v1); __syncthreads();
    for (int s = 128; s > 0; s >>= 1) {
        if (tid < s) red[tid] = fmaxf(red[tid], red[tid+s]);
        __syncthreads();
    }
    float m = red[0]; __syncthreads();
    float e0 = __expf(v0 - m), e1 = __expf(v1 - m);
    red[tid] = e0 + e1; __syncthreads();
    for (int s = 128; s > 0; s >>= 1) {
        if (tid < s) red[tid] += red[tid+s];
        __syncthreads();
    }
    float inv = 1.f / red[0];
    __nv_bfloat16* ph = g_ph + ((size_t)bh*TTT + qi)*TTT;
    __nv_bfloat16* pl = g_pl + ((size_t)bh*TTT + qi)*TTT;
    if (tid < n) {
        float p = e0 * inv;
        __nv_bfloat16 h, l; split_bf(p, h, l);
        ph[tid] = h; pl[tid] = l;
    }
    if (tid + 256 < n) {
        float p = e1 * inv;
        __nv_bfloat16 h, l; split_bf(p, h, l);
        ph[tid+256] = h; pl[tid+256] = l;
    }
}

// ---- k2c: ctx = P @ V, fused transpose into g_c ----
__global__ __launch_bounds__(256) void k2c() {
    int dt = blockIdx.x, qt = blockIdx.y, bh = blockIdx.z;
    const __nv_bfloat16* Ah = g_ph  + ((size_t)bh*TTT + qt*128)*TTT;
    const __nv_bfloat16* Al = g_pl  + ((size_t)bh*TTT + qt*128)*TTT;
    const __nv_bfloat16* Bh = g_vth + ((size_t)bh*HDD + dt*128)*TTT;
    const __nv_bfloat16* Bl = g_vtl + ((size_t)bh*HDD + dt*128)*TTT;
    mma_core<1>(Ah, Al, TTT, Bh, Bl, TTT, (qt + 1)*128, nullptr, 0, 0, 0, 1.f, bh, dt, qt);
}

// ==== k4: proj conv (mma, cp.async W) + PReLU + LN (102 KB -> 2 CTAs/SM) ====
#define K4_SMEM 104448
__global__ __launch_bounds__(256) void k4(
    const float* __restrict__ bias, const float* __restrict__ alp,
    const float* __restrict__ gam,  const float* __restrict__ bet)
{
    extern __shared__ __align__(16) uint8_t sm4[];
    __nv_bfloat16* sAh = (__nv_bfloat16*)(sm4);
    __nv_bfloat16* sAl = (__nv_bfloat16*)(sm4 + 17408);
    float* sY = (float*)(sm4 + 34816);
    __shared__ float r1[256], r2[256];
    uint32_t su = smem_u32(sm4);
    uint32_t uAh = su, uAl = su + 17408;
    uint32_t uWh = su + 34816, uWl = su + 34816 + 34816;

    int tid = threadIdx.x, lane = tid & 31, wid = tid >> 5;
    int wm = wid >> 2, wn = wid & 3;
    int t2 = blockIdx.x, b = blockIdx.y;

    {
        int r = tid >> 1, hf = tid & 1;
        const uint4* sh = (const uint4*)g_wphb + r*16 + hf*8;
        const uint4* sl = (const uint4*)g_wplb + r*16 + hf*8;
        uint32_t dh = uWh + (uint32_t)(r*SROWK*2 + hf*128);
        #pragma unroll
        for (int j = 0; j < 8; ++j) {
            cpa16(dh + j*16,         sh + j);
            cpa16(dh + 34816 + j*16, sl + j);
        }
        CPA_COMMIT();
    }

    {
        int c = tid >> 1, half = tid & 1;
        const float4* sp = (const float4*)(g_c + (((size_t)(b*128 + c))*TTT + t2)*FFQ + half*32);
        #pragma unroll
        for (int j = 0; j < 8; ++j) {
            float4 v = sp[j];
            int f0 = half*32 + j*4;
            float vv[4] = {v.x, v.y, v.z, v.w};
            #pragma unroll
            for (int jj = 0; jj < 4; ++jj) {
                __nv_bfloat16 h, l; split_bf(vv[jj], h, l);
                sAh[(f0+jj)*SROWK + c] = h;
                sAl[(f0+jj)*SROWK + c] = l;
            }
        }
    }
    cpa_wait<0>();
    __syncthreads();

    float acc[2][4][4];
    #pragma unroll
    for (int i = 0; i < 2; ++i)
        #pragma unroll
        for (int j = 0; j < 4; ++j)
            #pragma unroll
            for (int q = 0; q < 4; ++q) acc[i][j][q] = 0.f;

    uint32_t aoff = (uint32_t)(((wm*32 + (lane & 15))*SROWK + (lane >> 4)*8) * 2);
    uint32_t boff = (uint32_t)(((wn*32 + ((lane & 7) + ((lane >> 4) << 3)))*SROWK + ((lane >> 3) & 1)*8) * 2);

    #pragma unroll
    for (int kk = 0; kk < 8; ++kk) {
        uint32_t bhf[4][2], blf[4][2];
        #pragma unroll
        for (int ng = 0; ng < 2; ++ng) {
            uint32_t r4[4];
            ldsm4(r4, uWh + boff + ng*(16*SROWK*2) + kk*32);
            bhf[ng*2][0] = r4[0]; bhf[ng*2][1] = r4[1];
            bhf[ng*2+1][0] = r4[2]; bhf[ng*2+1][1] = r4[3];
            ldsm4(r4, uWl + boff + ng*(16*SROWK*2) + kk*32);
            blf[ng*2][0] = r4[0]; blf[ng*2][1] = r4[1];
            blf[ng*2+1][0] = r4[2]; blf[ng*2+1][1] = r4[3];
        }
        #pragma unroll
        for (int mf = 0; mf < 2; ++mf) {
            uint32_t ah[4], al[4];
            ldsm4(ah, uAh + aoff + mf*(16*SROWK*2) + kk*32);
            ldsm4(al, uAl + aoff + mf*(16*SROWK*2) + kk*32);
            #pragma unroll
            for (int nf = 0; nf < 4; ++nf) {
                mmabf(acc[mf][nf], ah, bhf[nf]);
                mmabf(acc[mf][nf], ah, blf[nf]);
                mmabf(acc[mf][nf], al, bhf[nf]);
            }
        }
    }

    float alpha = alp[0];
    float ls = 0.f, lq = 0.f;
    #pragma unroll
    for (int mf = 0; mf < 2; ++mf)
        #pragma unroll
        for (int nf = 0; nf < 4; ++nf) {
            int o0 = wn*32 + nf*8 + (lane & 3)*2;
            float b0 = bias[o0], b1 = bias[o0+1];
            #pragma unroll
            for (int h = 0; h < 2; ++h) {
                float v0 = acc[mf][nf][2*h] + b0;
                float v1 = acc[mf][nf][2*h+1] + b1;
                v0 = v0 >= 0.f ? v0 : alpha*v0;
                v1 = v1 >= 0.f ? v1 : alpha*v1;
                acc[mf][nf][2*h] = v0; acc[mf][nf][2*h+1] = v1;
                ls += v0 + v1; lq += v0*v0 + v1*v1;
            }
        }
    r1[tid] = ls; r2[tid] = lq;
    __syncthreads();
    for (int s = 128; s > 0; s >>= 1) {
        if (tid < s) { r1[tid] += r1[tid+s]; r2[tid] += r2[tid+s]; }
        __syncthreads();
    }
    const float invN = 1.f / (float)CF;
    float mu = r1[0]*invN, var = r2[0]*invN - mu*mu;
    float rstd = rsqrtf(var + EPSV);

    __syncthreads();
    #pragma unroll
    for (int mf = 0; mf < 2; ++mf)
        #pragma unroll
        for (int nf = 0; nf < 4; ++nf) {
            int o0 = wn*32 + nf*8 + (lane & 3)*2;
            #pragma unroll
            for (int h = 0; h < 2; ++h) {
                int f = wm*32 + mf*16 + h*8 + (lane >> 2);
                int gi0 = o0*64 + f, gi1 = gi0 + 64;
                sY[gi0] = (acc[mf][nf][2*h]   - mu)*rstd*gam[gi0] + bet[gi0];
                sY[gi1] = (acc[mf][nf][2*h+1] - mu)*rstd*gam[gi1] + bet[gi1];
            }
        }
    __syncthreads();

    float* yrow = g_y + ((size_t)b*TTT + t2)*CF;
    const float4* sY4 = (const float4*)sY;
    float4* yr4 = (float4*)yrow;
    #pragma unroll
    for (int k = 0; k < 8; ++k) yr4[tid + k*256] = sY4[tid + k*256];
}

// ---- g_y [b][t2][cf] -> out [b][cf][t2] ----
__global__ void k5(float* __restrict__ out) {
    __shared__ float tl[32][33];
    int b = blockIdx.z, t0 = blockIdx.x*32, r0 = blockIdx.y*32;
    const float* s = g_y + (size_t)b*TTT*CF;
    for (int i = threadIdx.y; i < 32; i += 8)
        tl[i][threadIdx.x] = s[(size_t)(t0+i)*CF + r0 + threadIdx.x];
    __syncthreads();
    float* d = out + (size_t)b*CF*TTT;
    for (int i = threadIdx.y; i < 32; i += 8)
        d[(size_t)(r0+i)*TTT + t0 + threadIdx.x] = tl[threadIdx.x][i];
}

extern "C" void kernel_launch(void* const* d_in, const int* in_sizes, int n_in,
                              void* d_out, int out_size) {
    const float* x   = (const float*)d_in[0];
    const float* qw  = (const float*)d_in[1];
    const float* qb  = (const float*)d_in[2];
    const float* qa  = (const float*)d_in[3];
    const float* qg  = (const float*)d_in[4];
    const float* qbe = (const float*)d_in[5];
    const float* pw  = (const float*)d_in[6];
    const float* pb  = (const float*)d_in[7];
    const float* pa  = (const float*)d_in[8];
    const float* pg  = (const float*)d_in[9];
    const float* pbe = (const float*)d_in[10];
    float* out = (float*)d_out;

    cudaFuncSetAttribute(k1,  cudaFuncAttributeMaxDynamicSharedMemorySize, K1_SMEM);
    cudaFuncSetAttribute(k2a, cudaFuncAttributeMaxDynamicSharedMemorySize, SMEMSZ);
    cudaFuncSetAttribute(k2c, cudaFuncAttributeMaxDynamicSharedMemorySize, SMEMSZ);
    cudaFuncSetAttribute(k4,  cudaFuncAttributeMaxDynamicSharedMemorySize, K4_SMEM);

    dim3 tb(32, 8);
    kW <<<192, 256>>>(qw, pw);
    k0 <<<dim3(16, 256, 4), tb>>>(x);
    k1 <<<dim3(512, 4), 256, K1_SMEM>>>(qb, qa, qg, qbe);
    k1v<<<dim3(16, 32, 32), tb>>>();
    k2a<<<dim3(4, 4, 32), 256, SMEMSZ>>>();
    k2b<<<dim3(512, 32), 256>>>();
    k2c<<<dim3(8, 4, 32), 256, SMEMSZ>>>();
    k4 <<<dim3(512, 4), 256, K4_SMEM>>>(pb, pa, pg, pbe);
    k5 <<<dim3(16, 256, 4), tb>>>(out);
}